// round 12
// baseline (speedup 1.0000x reference)
#include <cuda_runtime.h>

// Static device scratch (no allocation allowed anywhere). Zero at module
// load; every invocation returns it to zero (finalizers atomicExch accum
// columns to 0 and reset counters), so graph replays start clean.
#define MAX_SEGS   8192
#define MAX_D      256
#define HALVES_MAX (MAX_D / 128)
#define CHUNK_MAX  512
#define LOG_EPS    (-27.631021115928547f)   // log(1e-12)

__device__ float g_accum[MAX_SEGS * MAX_D];          // 8 MB
__device__ int   g_cnt[MAX_SEGS * HALVES_MAX];       // per (seg, col-half)

__device__ __forceinline__ int load_seg_id(const void* batch, int is64, int idx) {
    return is64 ? (int)((const long long*)batch)[idx]
                : ((const int*)batch)[idx];
}

// Warp-collective lower_bound: smallest i in [0,n] with batch[i] >= target.
__device__ __forceinline__ int warp_lower_bound(const void* batch, int is64,
                                                int n, int target, int lane) {
    int lo = 0, hi = n;
    while (hi - lo > 32) {
        int chunk = (hi - lo + 31) >> 5;
        int idx   = lo + lane * chunk;
        bool lt   = false;
        if (idx < hi) lt = load_seg_id(batch, is64, idx) < target;
        unsigned bal = __ballot_sync(0xFFFFFFFFu, lt);
        if (bal == 0) { hi = lo; break; }
        int l     = 31 - __clz(bal);
        int newlo = lo + l * chunk + 1;
        int newhi = lo + (l + 1) * chunk;
        hi = newhi < hi ? newhi : hi;
        lo = newlo;
    }
    if (hi <= lo) return lo;
    bool ge = false;
    int idx = lo + lane;
    if (idx < hi) ge = load_seg_id(batch, is64, idx) >= target;
    unsigned bal = __ballot_sync(0xFFFFFFFFu, ge);
    return bal ? (lo + __ffs(bal) - 1) : hi;
}

__device__ __forceinline__ void acc4(float4 v, float a[4]) {
    a[0] += __expf(v.x);
    a[1] += __expf(v.y);
    a[2] += __expf(v.z);
    a[3] += __expf(v.w);
}

// ---------------------------------------------------------------------------
// One block per (uniform row-chunk, 128-column half): perfectly balanced
// streaming (R8 hot loop, unchanged), then distributed finalization:
// per-(segment,half) contributor counters; the completing contributor does
// log+store+reset for those 128 columns. No epilogue kernel, no grid barrier.
// ---------------------------------------------------------------------------
__global__ __launch_bounds__(128, 8)
void pool_sum_kernel(const float* __restrict__ feats,
                     const void* __restrict__ batch,
                     float* __restrict__ out,
                     int n, int D, int G, int R, int H) {
    __shared__ int   sh_is64;
    __shared__ int   sm_seg[CHUNK_MAX];
    __shared__ short sm_bnd[CHUNK_MAX];
    __shared__ int   sm_previd;

    const int lane = threadIdx.x & 31;
    const int rg   = threadIdx.x >> 5;            // warp / row-group 0..3

    // Dtype probe (warp 0): int64 values in [0,G) => odd 32-bit words are all
    // zero high-halves; any nonzero sampled odd word => int32.
    if (rg == 0) {
        const int* b32 = (const int*)batch;
        int limit = n < 8192 ? n : 8192;
        int step  = limit / 32; if (step < 2) step = 2;
        int idx   = lane * step + 1;
        if (idx >= limit) idx = limit - 1;
        idx |= 1;
        if (idx >= limit) idx -= 2;
        int v = (idx >= 0) ? b32[idx] : 0;
        unsigned nz = __ballot_sync(0xFFFFFFFFu, v != 0);
        if (lane == 0) sh_is64 = (nz == 0) ? 1 : 0;
    }
    __syncthreads();
    const int is64 = sh_is64;

    const int r0 = blockIdx.x * R;
    int cnt = n - r0;
    if (cnt > R) cnt = R;
    if (cnt <= 0) return;

    // Stage this chunk's segment ids (clamped) + the id of row r0-1.
    for (int i = threadIdx.x; i < cnt; i += 128) {
        int sg = load_seg_id(batch, is64, r0 + i);
        if (sg < 0) sg = 0;
        if (sg > G - 1) sg = G - 1;
        sm_seg[i] = sg;
    }
    if (threadIdx.x == 0) {
        int pv = (r0 > 0) ? load_seg_id(batch, is64, r0 - 1) : -1;
        if (pv < -1) pv = -1;
        if (pv > G - 1) pv = G - 1;
        sm_previd = pv;
    }
    __syncthreads();

    const int h      = blockIdx.y;
    const int colblk = h * 128;
    const int c4     = (colblk >> 2) + lane;
    const int col0   = colblk + lane * 4;

    float a[4] = {0.f, 0.f, 0.f, 0.f};
    int acc_seg = (rg < cnt) ? sm_seg[rg] : -1;

    const size_t rstride = (size_t)(D >> 2);
    const float4* __restrict__ p =
        (const float4*)feats + (size_t)(r0 + rg) * rstride + c4;

#define CONSUME(v, lr)                                                        \
    do {                                                                      \
        int _sg = sm_seg[(lr)];                                               \
        if (_sg != acc_seg) {  /* warp-uniform, rare */                       \
            float* dst = &g_accum[(size_t)acc_seg * D + col0];                \
            atomicAdd(dst + 0, a[0]); atomicAdd(dst + 1, a[1]);               \
            atomicAdd(dst + 2, a[2]); atomicAdd(dst + 3, a[3]);               \
            a[0] = a[1] = a[2] = a[3] = 0.f;                                  \
            acc_seg = _sg;                                                    \
        }                                                                     \
        acc4((v), a);                                                         \
    } while (0)

    int lr = rg;                                  // local rows: rg, rg+4, ...
    if (lr + 12 < cnt) {
        float4 a0 = __ldg(p);
        float4 a1 = __ldg(p +  4 * rstride);
        float4 a2 = __ldg(p +  8 * rstride);
        float4 a3 = __ldg(p + 12 * rstride);
        p += 16 * rstride;
        lr += 16;
        for (; lr + 12 < cnt; lr += 16) {
            float4 b0 = __ldg(p);
            float4 b1 = __ldg(p +  4 * rstride);
            float4 b2 = __ldg(p +  8 * rstride);
            float4 b3 = __ldg(p + 12 * rstride);
            p += 16 * rstride;
            CONSUME(a0, lr - 16);
            CONSUME(a1, lr - 12);
            CONSUME(a2, lr -  8);
            CONSUME(a3, lr -  4);
            a0 = b0; a1 = b1; a2 = b2; a3 = b3;
        }
        CONSUME(a0, lr - 16);
        CONSUME(a1, lr - 12);
        CONSUME(a2, lr -  8);
        CONSUME(a3, lr -  4);
    }
    for (; lr < cnt; lr += 4) {
        float4 v = __ldg(p);
        p += 4 * rstride;
        CONSUME(v, lr);
    }
#undef CONSUME

    if (acc_seg >= 0) {
        float* dst = &g_accum[(size_t)acc_seg * D + col0];
        atomicAdd(dst + 0, a[0]); atomicAdd(dst + 1, a[1]);
        atomicAdd(dst + 2, a[2]); atomicAdd(dst + 3, a[3]);
    }

    __threadfence();          // release: all this block's adds visible
    __syncthreads();          // all 128 threads done flushing
    if (rg != 0) return;      // finalization is warp-0 only (no more barriers)

    const int previd = sm_previd;

    // ---- boundary scan (ordered): local starts of new segments ----
    int nb = 0;
    for (int base = 0; base < cnt; base += 32) {
        int i = base + lane;
        bool bnd = false;
        if (i < cnt) {
            int pr = (i == 0) ? previd : sm_seg[i - 1];
            bnd = (sm_seg[i] != pr);
        }
        unsigned bal = __ballot_sync(0xFFFFFFFFu, bnd);
        int ofs = __popc(bal & ((1u << lane) - 1));
        if (bnd) sm_bnd[nb + ofs] = (short)i;
        nb += __popc(bal);
    }
    __syncwarp();

    // ---- empty segments at owned boundaries (essentially never occurs) ----
    for (int k = 0; k < nb; ++k) {
        int i = sm_bnd[k];
        int b = sm_seg[i];
        int aid = (i == 0) ? previd : sm_seg[i - 1];
        for (int e = aid + 1; e < b; ++e)
            for (int c = lane; c < 128; c += 32)
                out[(size_t)e * D + colblk + c] = LOG_EPS;
    }
    if (r0 + cnt == n) {      // last chunk owns the trailing empty segments
        int aid = sm_seg[cnt - 1];
        for (int e = aid + 1; e <= G - 1; ++e)
            for (int c = lane; c < 128; c += 32)
                out[(size_t)e * D + colblk + c] = LOG_EPS;
    }

    // ---- per touched segment: counter; completing contributor finalizes ----
    {
        int k = 0;
        int ls = 0;
        while (ls < cnt) {
            while (k < nb && sm_bnd[k] <= ls) k++;
            int le  = (k < nb) ? sm_bnd[k] : cnt;
            int seg = sm_seg[ls];

            int start_g, end_g;
            bool start_local = !(ls == 0 && previd == seg);
            if (start_local) start_g = r0 + ls;
            else start_g = warp_lower_bound(batch, is64, n, seg, lane);
            if (le < cnt || r0 + cnt == n) end_g = r0 + le;
            else end_g = warp_lower_bound(batch, is64, n, seg + 1, lane);

            int expected = (end_g - 1) / R - start_g / R + 1;

            int old = 0;
            if (lane == 0) old = atomicAdd(&g_cnt[seg * H + h], 1);
            old = __shfl_sync(0xFFFFFFFFu, old, 0);

            if (old == expected - 1) {
                __threadfence();  // acquire: see all contributors' adds
                float* acc = &g_accum[(size_t)seg * D + colblk];
                for (int c = lane; c < 128; c += 32) {
                    float v = atomicExch(&acc[c], 0.0f);   // coherent read+reset
                    out[(size_t)seg * D + colblk + c] = __logf(fmaxf(v, 1e-12f));
                }
                if (lane == 0) atomicExch(&g_cnt[seg * H + h], 0);
            }
            ls = le;
        }
    }
}

// ---------------------------------------------------------------------------
// Inputs (metadata order): feats f32 [N*D], batch int [N], num_segments.
// ---------------------------------------------------------------------------
extern "C" void kernel_launch(void* const* d_in, const int* in_sizes, int n_in,
                              void* d_out, int out_size) {
    const float* feats = (const float*)d_in[0];
    const void*  batch = d_in[1];

    const int n = in_sizes[1];                 // rows (200000)
    const int D = in_sizes[0] / n;             // features (256)
    const int G = out_size / D;                // segments (512)

    // Uniform chunks sized for one wave: chunks * (D/128) <= 148*8 = 1184.
    const int H = D / 128;                     // column halves (2)
    const int max_chunks = 1184 / H;           // 592
    int R = (n + max_chunks - 1) / max_chunks; // 338
    if (R < 16) R = 16;
    if (R > CHUNK_MAX) R = CHUNK_MAX;
    const int nchunks = (n + R - 1) / R;

    dim3 grid(nchunks, H);
    pool_sum_kernel<<<grid, 128>>>(feats, batch, (float*)d_out,
                                   n, D, G, R, H);
}

// round 13
// speedup vs baseline: 1.1449x; 1.1449x over previous
#include <cuda_runtime.h>

// Static device scratch (no allocation allowed anywhere). Zero at module
// load; finalizers atomicExch every used accum column back to 0 and reset
// the counters, so each invocation (incl. graph replays) starts clean.
#define MAX_SEGS   8192
#define MAX_D      256
#define HALVES_MAX (MAX_D / 128)

__device__ float g_accum[MAX_SEGS * MAX_D];        // 8 MB
__device__ int   g_cnt[MAX_SEGS * HALVES_MAX];     // per (segment, col-half)

__device__ __forceinline__ int load_seg_id(const void* batch, int is64, int idx) {
    return is64 ? (int)((const long long*)batch)[idx]
                : ((const int*)batch)[idx];
}

// Warp-collective lower_bound: smallest i in [0,n] with batch[i] >= target.
__device__ __forceinline__ int warp_lower_bound(const void* batch, int is64,
                                                int n, int target, int lane) {
    int lo = 0, hi = n;
    while (hi - lo > 32) {
        int chunk = (hi - lo + 31) >> 5;
        int idx   = lo + lane * chunk;
        bool lt   = false;
        if (idx < hi) lt = load_seg_id(batch, is64, idx) < target;
        unsigned bal = __ballot_sync(0xFFFFFFFFu, lt);
        if (bal == 0) { hi = lo; break; }
        int l     = 31 - __clz(bal);
        int newlo = lo + l * chunk + 1;
        int newhi = lo + (l + 1) * chunk;
        hi = newhi < hi ? newhi : hi;
        lo = newlo;
    }
    if (hi <= lo) return lo;
    bool ge = false;
    int idx = lo + lane;
    if (idx < hi) ge = load_seg_id(batch, is64, idx) >= target;
    unsigned bal = __ballot_sync(0xFFFFFFFFu, ge);
    return bal ? (lo + __ffs(bal) - 1) : hi;
}

__device__ __forceinline__ void acc4(float4 v, float a[4]) {
    a[0] += __expf(v.x);
    a[1] += __expf(v.y);
    a[2] += __expf(v.z);
    a[3] += __expf(v.w);
}

// ---------------------------------------------------------------------------
// One block per (segment, 128-col half, row-half). 64 threads =
// 32 float4-lanes x 2 row-groups. 2048 blocks, all resident (~14/SM),
// same warp count per SM as before but HALF the tail granularity.
// Pure R11 streaming loop over a fixed contiguous row range; two-contributor
// atomic merge per (segment, col-half); second arriver finalizes (log+store)
// and resets the scratch. Empty segments finalize to log(1e-12) for free.
// ---------------------------------------------------------------------------
__global__ __launch_bounds__(64, 16)
void pool_lse_kernel(const float* __restrict__ feats,
                     const void* __restrict__ batch,
                     float* __restrict__ out,
                     int n, int D, int G, int H) {
    __shared__ int sh_is64;
    __shared__ int sh_bounds[2];
    __shared__ int sh_fin;

    const int lane = threadIdx.x & 31;
    const int rg   = threadIdx.x >> 5;            // row group 0..1 (= warp)

    // Dtype probe (warp 0): int64 values in [0,G) => odd 32-bit words are all
    // zero high-halves; any nonzero sampled odd word => int32.
    if (rg == 0) {
        const int* b32 = (const int*)batch;
        int limit = n < 8192 ? n : 8192;
        int step  = limit / 32; if (step < 2) step = 2;
        int idx   = lane * step + 1;
        if (idx >= limit) idx = limit - 1;
        idx |= 1;
        if (idx >= limit) idx -= 2;
        int v = (idx >= 0) ? b32[idx] : 0;
        unsigned nz = __ballot_sync(0xFFFFFFFFu, v != 0);
        if (lane == 0) sh_is64 = (nz == 0) ? 1 : 0;
    }
    __syncthreads();
    const int is64 = sh_is64;

    const int g = blockIdx.x;
    const int h = blockIdx.y;                     // column half
    const int z = blockIdx.z;                     // row half

    // Warps 0/1 compute lower_bound(g) / lower_bound(g+1) in parallel.
    {
        int r = warp_lower_bound(batch, is64, n, g + rg, lane);
        if (lane == 0) sh_bounds[rg] = r;
    }
    __syncthreads();

    const int start = sh_bounds[0];
    const int end   = sh_bounds[1];
    const int len   = end - start;
    // Row-half ranges: z=0 -> [start, start+len/2), z=1 -> [start+len/2, end).
    const int rs = start + ((len >> 1) & (z ? ~0 : 0)) + (z ? 0 : 0);
    const int rs_ = z ? (start + (len >> 1)) : start;
    const int re  = z ? end : (start + (len >> 1));
    (void)rs;

    const int colblk = h * 128;
    const int c4     = (colblk >> 2) + lane;
    const int col0   = colblk + lane * 4;

    float s[4] = {0.f, 0.f, 0.f, 0.f};
    float t[4] = {0.f, 0.f, 0.f, 0.f};

    const size_t rstride = (size_t)(D >> 2);      // float4s per row
    const float4* __restrict__ p =
        (const float4*)feats + (size_t)(rs_ + rg) * rstride + c4;

    int r = rs_ + rg;                             // rows: r, r+2, r+4, ...
    if (r + 6 < re) {
        // Prologue: 4 in-flight LDG.128 (rows r, r+2, r+4, r+6).
        float4 a0 = __ldg(p);
        float4 a1 = __ldg(p + 2 * rstride);
        float4 a2 = __ldg(p + 4 * rstride);
        float4 a3 = __ldg(p + 6 * rstride);
        p += 8 * rstride;
        r += 8;
        for (; r + 6 < re; r += 8) {
            float4 b0 = __ldg(p);
            float4 b1 = __ldg(p + 2 * rstride);
            float4 b2 = __ldg(p + 4 * rstride);
            float4 b3 = __ldg(p + 6 * rstride);
            p += 8 * rstride;
            acc4(a0, s);
            acc4(a1, t);
            acc4(a2, s);
            acc4(a3, t);
            a0 = b0; a1 = b1; a2 = b2; a3 = b3;
        }
        acc4(a0, s);
        acc4(a1, t);
        acc4(a2, s);
        acc4(a3, t);
    }
    for (; r < re; r += 2) {
        float4 v = __ldg(p);
        p += 2 * rstride;
        acc4(v, s);
    }

    // ---- flush partial into global accumulator (both warps, spread) ----
    {
        float* dst = &g_accum[(size_t)g * D + col0];
        atomicAdd(dst + 0, s[0] + t[0]);
        atomicAdd(dst + 1, s[1] + t[1]);
        atomicAdd(dst + 2, s[2] + t[2]);
        atomicAdd(dst + 3, s[3] + t[3]);
    }

    // ---- two-contributor merge: second arriver finalizes ----
    __threadfence();                  // release: our adds visible first
    __syncthreads();
    if (threadIdx.x == 0) {
        int old = atomicAdd(&g_cnt[g * H + h], 1);
        sh_fin = (old == 1) ? 1 : 0;
    }
    __syncthreads();
    if (sh_fin) {
        __threadfence();              // acquire: see both contributors' adds
        float* acc = &g_accum[(size_t)g * D + colblk];
        float* o   = &out[(size_t)g * D + colblk];
        for (int c = threadIdx.x; c < 128; c += 64) {
            float v = atomicExch(&acc[c], 0.0f);   // coherent read + reset
            o[c] = __logf(fmaxf(v, 1e-12f));       // empty seg -> log(1e-12)
        }
        if (threadIdx.x == 0) atomicExch(&g_cnt[g * H + h], 0);
    }
}

// ---------------------------------------------------------------------------
// Inputs (metadata order): feats f32 [N*D], batch int [N], num_segments.
// ---------------------------------------------------------------------------
extern "C" void kernel_launch(void* const* d_in, const int* in_sizes, int n_in,
                              void* d_out, int out_size) {
    const float* feats = (const float*)d_in[0];
    const void*  batch = d_in[1];

    const int n = in_sizes[1];                 // rows (200000)
    const int D = in_sizes[0] / n;             // features (256)
    const int G = out_size / D;                // segments (512)
    const int H = D / 128;                     // column halves (2)

    dim3 grid(G, H, 2);                        // (segment, col-half, row-half)
    pool_lse_kernel<<<grid, 64>>>(feats, batch, (float*)d_out, n, D, G, H);
}